// round 2
// baseline (speedup 1.0000x reference)
#include <cuda_runtime.h>
#include <cstdint>

#define BB        8192
#define TDIM      256
#define PDIM      72
#define HID       256
#define G3        768
#define IN_DIM    328
#define ROWS      64
#define NTHREADS  512

// Transposed weights (k-major, coalesced over output index) + precomputed text projection.
__device__ float g_Wt_ih[IN_DIM * G3];     // [k][j] = W_ih[j][k]
__device__ float g_Wt_hh[HID * G3];        // [k][j] = W_hh[j][k]
__device__ float g_Wt1[HID * HID];         // [k][j] = W1[j][k]
__device__ float g_Wt2[HID * PDIM];        // [k][p] = W2[p][k]
__device__ float g_gitext[(size_t)BB * G3];// b_ih[j] + text[b]·W_ih[j,:256]

__global__ void prep_kernel(const float* __restrict__ Wih, const float* __restrict__ Whh,
                            const float* __restrict__ W1,  const float* __restrict__ W2) {
    int idx = blockIdx.x * blockDim.x + threadIdx.x;
    int n1 = G3 * IN_DIM;
    if (idx < n1) { int j = idx / IN_DIM, k = idx % IN_DIM; g_Wt_ih[k * G3 + j] = Wih[idx]; return; }
    idx -= n1;
    int n2 = G3 * HID;
    if (idx < n2) { int j = idx / HID, k = idx % HID; g_Wt_hh[k * G3 + j] = Whh[idx]; return; }
    idx -= n2;
    int n3 = HID * HID;
    if (idx < n3) { int j = idx / HID, k = idx % HID; g_Wt1[k * HID + j] = W1[idx]; return; }
    idx -= n3;
    int n4 = PDIM * HID;
    if (idx < n4) { int p = idx / HID, k = idx % HID; g_Wt2[k * PDIM + p] = W2[idx]; return; }
}

__device__ __forceinline__ float sigf(float x)      { return 1.0f / (1.0f + __expf(-x)); }
__device__ __forceinline__ float tanh_fast(float x) { return 2.0f / (1.0f + __expf(-2.0f * x)) - 1.0f; }

__global__ void __launch_bounds__(NTHREADS, 1)
gru_kernel(const float* __restrict__ text,
           const float* __restrict__ prev_poses,
           const float* __restrict__ hidden,
           const int*   __restrict__ steps_ptr,
           const float* __restrict__ b_ih,
           const float* __restrict__ b_hh,
           const float* __restrict__ b1,
           const float* __restrict__ b2,
           float* __restrict__ out)
{
    extern __shared__ float sm[];
    float* hA = sm;                   // [64][256]
    float* hB = hA + ROWS * HID;      // [64][256]
    float* rb = hB + ROWS * HID;      // [64][256]  r-buffer / text tile / mlp buffer
    float* ps = rb + ROWS * HID;      // [64][72]   running poses

    const int tid  = threadIdx.x;
    const int i    = tid & 255;       // gate / hidden index
    const int half = tid >> 8;        // row half (0/1)
    const int m0   = half * 32;
    const int base = blockIdx.x * ROWS;
    const int S    = *steps_ptr;

    // ---- load state + text tile ----
    for (int idx = tid; idx < ROWS * HID;  idx += NTHREADS) hA[idx] = hidden[(size_t)base * HID + idx];
    for (int idx = tid; idx < ROWS * PDIM; idx += NTHREADS) ps[idx] = prev_poses[(size_t)base * PDIM + idx];
    for (int idx = tid; idx < ROWS * TDIM; idx += NTHREADS) rb[idx] = text[(size_t)base * TDIM + idx];
    __syncthreads();

    // ---- precompute gi_text for this CTA's 64 rows (step-invariant) ----
    for (int jc = 0; jc < 3; jc++) {
        int j = jc * 256 + i;
        float acc[32];
        float bv = b_ih[j];
        #pragma unroll
        for (int m = 0; m < 32; m++) acc[m] = bv;
        for (int k = 0; k < TDIM; k += 4) {
            float w0 = g_Wt_ih[(k + 0) * G3 + j];
            float w1 = g_Wt_ih[(k + 1) * G3 + j];
            float w2 = g_Wt_ih[(k + 2) * G3 + j];
            float w3 = g_Wt_ih[(k + 3) * G3 + j];
            #pragma unroll
            for (int m = 0; m < 32; m++) {
                const float4 tv = *(const float4*)&rb[(m0 + m) * TDIM + k];
                acc[m] += tv.x * w0 + tv.y * w1 + tv.z * w2 + tv.w * w3;
            }
        }
        #pragma unroll
        for (int m = 0; m < 32; m++)
            g_gitext[(size_t)(base + m0 + m) * G3 + j] = acc[m];
    }
    __syncthreads();

    float* hc = hA;
    float* hn = hB;

    for (int t = 0; t < S; t++) {
        // ---- Phase R: r[m][i] = sigmoid(gi_r + gh_r) ----
        {
            float acc[32];
            float bv = b_hh[i];
            #pragma unroll
            for (int m = 0; m < 32; m++)
                acc[m] = g_gitext[(size_t)(base + m0 + m) * G3 + i] + bv;
            for (int k = 0; k < PDIM; k += 4) {
                float w0 = g_Wt_ih[(TDIM + k + 0) * G3 + i];
                float w1 = g_Wt_ih[(TDIM + k + 1) * G3 + i];
                float w2 = g_Wt_ih[(TDIM + k + 2) * G3 + i];
                float w3 = g_Wt_ih[(TDIM + k + 3) * G3 + i];
                #pragma unroll
                for (int m = 0; m < 32; m++) {
                    const float4 pv = *(const float4*)&ps[(m0 + m) * PDIM + k];
                    acc[m] += pv.x * w0 + pv.y * w1 + pv.z * w2 + pv.w * w3;
                }
            }
            for (int k = 0; k < HID; k += 4) {
                float w0 = g_Wt_hh[(k + 0) * G3 + i];
                float w1 = g_Wt_hh[(k + 1) * G3 + i];
                float w2 = g_Wt_hh[(k + 2) * G3 + i];
                float w3 = g_Wt_hh[(k + 3) * G3 + i];
                #pragma unroll
                for (int m = 0; m < 32; m++) {
                    const float4 hv = *(const float4*)&hc[(m0 + m) * HID + k];
                    acc[m] += hv.x * w0 + hv.y * w1 + hv.z * w2 + hv.w * w3;
                }
            }
            #pragma unroll
            for (int m = 0; m < 32; m++)
                rb[(m0 + m) * HID + i] = sigf(acc[m]);
        }
        __syncthreads();

        // ---- Phase ZN: z, n and h_new (two 16-row sub-passes to bound registers) ----
        #pragma unroll 1
        for (int sub = 0; sub < 2; sub++) {
            const int mb = m0 + sub * 16;
            float accz[16], achn[16], acni[16];
            const float bz = b_hh[256 + i];
            const float bn = b_hh[512 + i];
            #pragma unroll
            for (int m = 0; m < 16; m++) {
                const float* gp = &g_gitext[(size_t)(base + mb + m) * G3];
                accz[m] = gp[256 + i] + bz;
                acni[m] = gp[512 + i];
                achn[m] = bn;
            }
            for (int k = 0; k < PDIM; k += 4) {
                float wz0 = g_Wt_ih[(TDIM + k + 0) * G3 + 256 + i];
                float wz1 = g_Wt_ih[(TDIM + k + 1) * G3 + 256 + i];
                float wz2 = g_Wt_ih[(TDIM + k + 2) * G3 + 256 + i];
                float wz3 = g_Wt_ih[(TDIM + k + 3) * G3 + 256 + i];
                float wn0 = g_Wt_ih[(TDIM + k + 0) * G3 + 512 + i];
                float wn1 = g_Wt_ih[(TDIM + k + 1) * G3 + 512 + i];
                float wn2 = g_Wt_ih[(TDIM + k + 2) * G3 + 512 + i];
                float wn3 = g_Wt_ih[(TDIM + k + 3) * G3 + 512 + i];
                #pragma unroll
                for (int m = 0; m < 16; m++) {
                    const float4 pv = *(const float4*)&ps[(mb + m) * PDIM + k];
                    accz[m] += pv.x * wz0 + pv.y * wz1 + pv.z * wz2 + pv.w * wz3;
                    acni[m] += pv.x * wn0 + pv.y * wn1 + pv.z * wn2 + pv.w * wn3;
                }
            }
            for (int k = 0; k < HID; k += 4) {
                float wz0 = g_Wt_hh[(k + 0) * G3 + 256 + i];
                float wz1 = g_Wt_hh[(k + 1) * G3 + 256 + i];
                float wz2 = g_Wt_hh[(k + 2) * G3 + 256 + i];
                float wz3 = g_Wt_hh[(k + 3) * G3 + 256 + i];
                float wn0 = g_Wt_hh[(k + 0) * G3 + 512 + i];
                float wn1 = g_Wt_hh[(k + 1) * G3 + 512 + i];
                float wn2 = g_Wt_hh[(k + 2) * G3 + 512 + i];
                float wn3 = g_Wt_hh[(k + 3) * G3 + 512 + i];
                #pragma unroll
                for (int m = 0; m < 16; m++) {
                    const float4 hv = *(const float4*)&hc[(mb + m) * HID + k];
                    accz[m] += hv.x * wz0 + hv.y * wz1 + hv.z * wz2 + hv.w * wz3;
                    achn[m] += hv.x * wn0 + hv.y * wn1 + hv.z * wn2 + hv.w * wn3;
                }
            }
            #pragma unroll
            for (int m = 0; m < 16; m++) {
                float z  = sigf(accz[m]);
                float rv = rb[(mb + m) * HID + i];
                float n  = tanh_fast(acni[m] + rv * achn[m]);
                hn[(mb + m) * HID + i] = (1.0f - z) * n + z * hc[(mb + m) * HID + i];
            }
        }
        __syncthreads();

        // ---- Phase M1: mlp = relu(h_new @ W1^T + b1), into rb (r is dead) ----
        {
            float acc[32];
            float bv = b1[i];
            #pragma unroll
            for (int m = 0; m < 32; m++) acc[m] = bv;
            for (int k = 0; k < HID; k += 4) {
                float w0 = g_Wt1[(k + 0) * HID + i];
                float w1 = g_Wt1[(k + 1) * HID + i];
                float w2 = g_Wt1[(k + 2) * HID + i];
                float w3 = g_Wt1[(k + 3) * HID + i];
                #pragma unroll
                for (int m = 0; m < 32; m++) {
                    const float4 hv = *(const float4*)&hn[(m0 + m) * HID + k];
                    acc[m] += hv.x * w0 + hv.y * w1 + hv.z * w2 + hv.w * w3;
                }
            }
            #pragma unroll
            for (int m = 0; m < 32; m++)
                rb[(m0 + m) * HID + i] = fmaxf(acc[m], 0.0f);
        }
        __syncthreads();

        // ---- Phase M2: delta = mlp @ W2^T + b2 ; pose += delta ; emit ----
        for (int idx = tid; idx < ROWS * PDIM; idx += NTHREADS) {
            const int m = idx / PDIM;
            const int p = idx % PDIM;
            float acc = b2[p];
            const float* mr = &rb[m * HID];
            for (int k = 0; k < HID; k += 4) {
                acc += mr[k + 0] * g_Wt2[(k + 0) * PDIM + p]
                     + mr[k + 1] * g_Wt2[(k + 1) * PDIM + p]
                     + mr[k + 2] * g_Wt2[(k + 2) * PDIM + p]
                     + mr[k + 3] * g_Wt2[(k + 3) * PDIM + p];
            }
            const float np = ps[idx] + acc;
            ps[idx] = np;
            out[((size_t)(base + m) * S + t) * PDIM + p] = np;
        }
        __syncthreads();

        float* tmp = hc; hc = hn; hn = tmp;
    }

    // ---- final hidden state, appended after poses ----
    const size_t hoff = (size_t)BB * S * PDIM;
    for (int idx = tid; idx < ROWS * HID; idx += NTHREADS)
        out[hoff + (size_t)base * HID + idx] = hc[idx];
}

static const int SMEM_BYTES = (3 * ROWS * HID + ROWS * PDIM) * (int)sizeof(float); // 215040

extern "C" void kernel_launch(void* const* d_in, const int* in_sizes, int n_in,
                              void* d_out, int out_size) {
    const float* text   = (const float*)d_in[0];
    const float* prev   = (const float*)d_in[1];
    const float* hidden = (const float*)d_in[2];
    const int*   steps  = (const int*)  d_in[3];
    const float* W_ih   = (const float*)d_in[4];
    const float* W_hh   = (const float*)d_in[5];
    const float* b_ih   = (const float*)d_in[6];
    const float* b_hh   = (const float*)d_in[7];
    const float* W1     = (const float*)d_in[8];
    const float* b1     = (const float*)d_in[9];
    const float* W2     = (const float*)d_in[10];
    const float* b2     = (const float*)d_in[11];
    float* out = (float*)d_out;

    const int total = G3 * IN_DIM + G3 * HID + HID * HID + PDIM * HID;
    prep_kernel<<<(total + 255) / 256, 256>>>(W_ih, W_hh, W1, W2);

    cudaFuncSetAttribute(gru_kernel, cudaFuncAttributeMaxDynamicSharedMemorySize, SMEM_BYTES);
    gru_kernel<<<BB / ROWS, NTHREADS, SMEM_BYTES>>>(text, prev, hidden, steps,
                                                    b_ih, b_hh, b1, b2, out);
}

// round 3
// speedup vs baseline: 1.0176x; 1.0176x over previous
#include <cuda_runtime.h>
#include <cstdint>

#define BB        8192
#define TDIM      256
#define PDIM      72
#define HID       256
#define G3        768
#define IN_DIM    328
#define ROWS      64
#define NTHREADS  512

typedef unsigned long long u64;

// Weights repacked as float4 k-groups, k-major, coalesced over output index j.
// g_Wih4[kq*G3 + j] = W_ih[j][4kq .. 4kq+3]
__device__ float4 g_Wih4[(IN_DIM / 4) * G3];
__device__ float4 g_Whh4[(HID / 4) * G3];
__device__ float4 g_W14[(HID / 4) * HID];
__device__ float4 g_W24[(HID / 4) * PDIM];
__device__ float  g_gitext[(size_t)BB * G3];   // b_ih[j] + text[b]·W_ih[j,:256]

__global__ void prep_kernel(const float* __restrict__ Wih, const float* __restrict__ Whh,
                            const float* __restrict__ W1,  const float* __restrict__ W2) {
    int idx = blockIdx.x * blockDim.x + threadIdx.x;
    int n1 = (IN_DIM / 4) * G3;
    if (idx < n1) {
        int kq = idx / G3, j = idx % G3;
        const float* s = &Wih[j * IN_DIM + 4 * kq];
        g_Wih4[idx] = make_float4(s[0], s[1], s[2], s[3]);
        return;
    }
    idx -= n1;
    int n2 = (HID / 4) * G3;
    if (idx < n2) {
        int kq = idx / G3, j = idx % G3;
        const float* s = &Whh[j * HID + 4 * kq];
        g_Whh4[idx] = make_float4(s[0], s[1], s[2], s[3]);
        return;
    }
    idx -= n2;
    int n3 = (HID / 4) * HID;
    if (idx < n3) {
        int kq = idx / HID, j = idx % HID;
        const float* s = &W1[j * HID + 4 * kq];
        g_W14[idx] = make_float4(s[0], s[1], s[2], s[3]);
        return;
    }
    idx -= n3;
    int n4 = (HID / 4) * PDIM;
    if (idx < n4) {
        int kq = idx / PDIM, p = idx % PDIM;
        const float* s = &W2[p * HID + 4 * kq];
        g_W24[idx] = make_float4(s[0], s[1], s[2], s[3]);
    }
}

// ---- packed fp32 helpers (Blackwell f32x2) ----
__device__ __forceinline__ void fma2(u64& d, u64 a, u64 b) {
    asm("fma.rn.f32x2 %0, %1, %2, %0;" : "+l"(d) : "l"(a), "l"(b));
}
__device__ __forceinline__ u64 pack2(float lo, float hi) {
    u64 r; asm("mov.b64 %0, {%1, %2};" : "=l"(r) : "f"(lo), "f"(hi)); return r;
}
__device__ __forceinline__ float redu2(u64 v) {
    float lo, hi; asm("mov.b64 {%0, %1}, %2;" : "=f"(lo), "=f"(hi) : "l"(v));
    return lo + hi;
}

__device__ __forceinline__ float sigf(float x)      { return 1.0f / (1.0f + __expf(-x)); }
__device__ __forceinline__ float tanh_fast(float x) { return 2.0f / (1.0f + __expf(-2.0f * x)) - 1.0f; }

__global__ void __launch_bounds__(NTHREADS, 1)
gru_kernel(const float* __restrict__ text,
           const float* __restrict__ prev_poses,
           const float* __restrict__ hidden,
           const int*   __restrict__ steps_ptr,
           const float* __restrict__ b_ih,
           const float* __restrict__ b_hh,
           const float* __restrict__ b1,
           const float* __restrict__ b2,
           float* __restrict__ out)
{
    extern __shared__ float sm[];
    float* hA = sm;                   // [64][256]
    float* hB = hA + ROWS * HID;      // [64][256]
    float* rb = hB + ROWS * HID;      // [64][256]  text tile / acni scratch / mlp buffer
    float* ps = rb + ROWS * HID;      // [64][72]   running poses

    const int tid  = threadIdx.x;
    const int i    = tid & 255;       // gate / hidden index
    const int half = tid >> 8;        // row half (0/1)
    const int m0   = half * 32;
    const int base = blockIdx.x * ROWS;
    const int S    = *steps_ptr;

    // ---- load state + text tile ----
    for (int idx = tid; idx < ROWS * HID;  idx += NTHREADS) hA[idx] = hidden[(size_t)base * HID + idx];
    for (int idx = tid; idx < ROWS * PDIM; idx += NTHREADS) ps[idx] = prev_poses[(size_t)base * PDIM + idx];
    for (int idx = tid; idx < ROWS * TDIM; idx += NTHREADS) rb[idx] = text[(size_t)base * TDIM + idx];
    __syncthreads();

    // ---- precompute gi_text (step-invariant) ----
    for (int jc = 0; jc < 3; jc++) {
        const int j  = jc * 256 + i;
        const float bv = b_ih[j];
        #pragma unroll 1
        for (int sub = 0; sub < 2; sub++) {
            const int mb = m0 + sub * 16;
            u64 acc[16];
            #pragma unroll
            for (int m = 0; m < 16; m++) acc[m] = pack2(bv, 0.0f);
            #pragma unroll 1
            for (int kq = 0; kq < TDIM / 4; kq++) {
                const ulonglong2 wv = *(const ulonglong2*)&g_Wih4[kq * G3 + j];
                #pragma unroll
                for (int m = 0; m < 16; m++) {
                    const ulonglong2 tv = *(const ulonglong2*)&rb[(mb + m) * TDIM + 4 * kq];
                    fma2(acc[m], tv.x, wv.x);
                    fma2(acc[m], tv.y, wv.y);
                }
            }
            #pragma unroll
            for (int m = 0; m < 16; m++)
                g_gitext[(size_t)(base + mb + m) * G3 + j] = redu2(acc[m]);
        }
    }
    __syncthreads();

    float* hc = hA;
    float* hn = hB;

    for (int t = 0; t < S; t++) {
        // ================= merged gate phase: r, z, n, h_new in one pass =================
        const float br  = b_hh[i];
        const float bz  = b_hh[256 + i];
        const float bnh = b_hh[512 + i];
        #pragma unroll 1
        for (int sub = 0; sub < 2; sub++) {
            const int mb = m0 + sub * 16;
            u64 accr[16], accz[16], accn[16];
            #pragma unroll
            for (int m = 0; m < 16; m++) {
                const float* gp = &g_gitext[(size_t)(base + mb + m) * G3];
                accr[m] = pack2(gp[i] + br, 0.0f);
                accz[m] = pack2(gp[256 + i] + bz, 0.0f);
                accn[m] = pack2(gp[512 + i], 0.0f);     // i_n accumulator (pose part)
            }
            // pose contribution (k in [256,328))
            #pragma unroll 1
            for (int kq = 0; kq < PDIM / 4; kq++) {
                const int kb = (TDIM / 4 + kq) * G3;
                const ulonglong2 wr = *(const ulonglong2*)&g_Wih4[kb + i];
                const ulonglong2 wz = *(const ulonglong2*)&g_Wih4[kb + 256 + i];
                const ulonglong2 wn = *(const ulonglong2*)&g_Wih4[kb + 512 + i];
                #pragma unroll
                for (int m = 0; m < 16; m++) {
                    const ulonglong2 pv = *(const ulonglong2*)&ps[(mb + m) * PDIM + 4 * kq];
                    fma2(accr[m], pv.x, wr.x); fma2(accr[m], pv.y, wr.y);
                    fma2(accz[m], pv.x, wz.x); fma2(accz[m], pv.y, wz.y);
                    fma2(accn[m], pv.x, wn.x); fma2(accn[m], pv.y, wn.y);
                }
            }
            // stash i_n scalar to scratch, reuse accn for h·W_hh_n
            #pragma unroll
            for (int m = 0; m < 16; m++) {
                rb[(mb + m) * HID + i] = redu2(accn[m]);
                accn[m] = pack2(bnh, 0.0f);
            }
            // hidden contribution (k in [0,256))
            #pragma unroll 1
            for (int kq = 0; kq < HID / 4; kq++) {
                const int kb = kq * G3;
                const ulonglong2 wr = *(const ulonglong2*)&g_Whh4[kb + i];
                const ulonglong2 wz = *(const ulonglong2*)&g_Whh4[kb + 256 + i];
                const ulonglong2 wn = *(const ulonglong2*)&g_Whh4[kb + 512 + i];
                #pragma unroll
                for (int m = 0; m < 16; m++) {
                    const ulonglong2 hv = *(const ulonglong2*)&hc[(mb + m) * HID + 4 * kq];
                    fma2(accr[m], hv.x, wr.x); fma2(accr[m], hv.y, wr.y);
                    fma2(accz[m], hv.x, wz.x); fma2(accz[m], hv.y, wz.y);
                    fma2(accn[m], hv.x, wn.x); fma2(accn[m], hv.y, wn.y);
                }
            }
            // gate math + blend
            #pragma unroll
            for (int m = 0; m < 16; m++) {
                const float r  = sigf(redu2(accr[m]));
                const float z  = sigf(redu2(accz[m]));
                const float nn = tanh_fast(rb[(mb + m) * HID + i] + r * redu2(accn[m]));
                hn[(mb + m) * HID + i] = (1.0f - z) * nn + z * hc[(mb + m) * HID + i];
            }
        }
        __syncthreads();

        // ================= M1: mlp = relu(h_new @ W1^T + b1) -> rb =================
        {
            const int q  = tid >> 7;       // row quarter (16 rows)
            const int i2 = tid & 127;      // column pair (i2, i2+128)
            u64 a0[16], a1[16];
            const float b10 = b1[i2], b11 = b1[i2 + 128];
            #pragma unroll
            for (int m = 0; m < 16; m++) { a0[m] = pack2(b10, 0.0f); a1[m] = pack2(b11, 0.0f); }
            #pragma unroll 1
            for (int kq = 0; kq < HID / 4; kq++) {
                const ulonglong2 w0 = *(const ulonglong2*)&g_W14[kq * HID + i2];
                const ulonglong2 w1 = *(const ulonglong2*)&g_W14[kq * HID + i2 + 128];
                #pragma unroll
                for (int m = 0; m < 16; m++) {
                    const ulonglong2 hv = *(const ulonglong2*)&hn[(q * 16 + m) * HID + 4 * kq];
                    fma2(a0[m], hv.x, w0.x); fma2(a0[m], hv.y, w0.y);
                    fma2(a1[m], hv.x, w1.x); fma2(a1[m], hv.y, w1.y);
                }
            }
            #pragma unroll
            for (int m = 0; m < 16; m++) {
                rb[(q * 16 + m) * HID + i2]       = fmaxf(redu2(a0[m]), 0.0f);
                rb[(q * 16 + m) * HID + i2 + 128] = fmaxf(redu2(a1[m]), 0.0f);
            }
        }
        __syncthreads();

        // ================= M2: delta = mlp @ W2^T + b2 ; pose += delta ; emit =====
        #pragma unroll 1
        for (int it = 0; it < (ROWS * PDIM) / NTHREADS; it++) {
            const int idx = tid + it * NTHREADS;
            const int m = idx / PDIM;
            const int p = idx % PDIM;
            u64 acc = pack2(b2[p], 0.0f);
            const float* mr = &rb[m * HID];
            #pragma unroll 4
            for (int kq = 0; kq < HID / 4; kq++) {
                const ulonglong2 mv = *(const ulonglong2*)&mr[4 * kq];
                const ulonglong2 wv = *(const ulonglong2*)&g_W24[kq * PDIM + p];
                fma2(acc, mv.x, wv.x);
                fma2(acc, mv.y, wv.y);
            }
            const float np = ps[idx] + redu2(acc);
            ps[idx] = np;
            out[((size_t)(base + m) * S + t) * PDIM + p] = np;
        }
        __syncthreads();

        float* tmp = hc; hc = hn; hn = tmp;
    }

    // ---- final hidden state, appended after poses ----
    const size_t hoff = (size_t)BB * S * PDIM;
    for (int idx = tid; idx < ROWS * HID; idx += NTHREADS)
        out[hoff + (size_t)base * HID + idx] = hc[idx];
}

static const int SMEM_BYTES = (3 * ROWS * HID + ROWS * PDIM) * (int)sizeof(float); // 215040

extern "C" void kernel_launch(void* const* d_in, const int* in_sizes, int n_in,
                              void* d_out, int out_size) {
    const float* text   = (const float*)d_in[0];
    const float* prev   = (const float*)d_in[1];
    const float* hidden = (const float*)d_in[2];
    const int*   steps  = (const int*)  d_in[3];
    const float* W_ih   = (const float*)d_in[4];
    const float* W_hh   = (const float*)d_in[5];
    const float* b_ih   = (const float*)d_in[6];
    const float* b_hh   = (const float*)d_in[7];
    const float* W1     = (const float*)d_in[8];
    const float* b1     = (const float*)d_in[9];
    const float* W2     = (const float*)d_in[10];
    const float* b2     = (const float*)d_in[11];
    float* out = (float*)d_out;

    const int total = (IN_DIM / 4) * G3 + (HID / 4) * G3 + (HID / 4) * HID + (HID / 4) * PDIM;
    prep_kernel<<<(total + 255) / 256, 256>>>(W_ih, W_hh, W1, W2);

    cudaFuncSetAttribute(gru_kernel, cudaFuncAttributeMaxDynamicSharedMemorySize, SMEM_BYTES);
    gru_kernel<<<BB / ROWS, NTHREADS, SMEM_BYTES>>>(text, prev, hidden, steps,
                                                    b_ih, b_hh, b1, b2, out);
}